// round 15
// baseline (speedup 1.0000x reference)
#include <cuda_runtime.h>
#include <cuda_fp16.h>
#include <math.h>

#define DIMS 1024
#define KSZ  128
#define SEQ  2048
#define BATCH 8
#define M_TOTAL (BATCH*SEQ)     // 16384
#define OUTD (DIMS + KSZ)       // 1152

// scratch (allocation-free rule: __device__ globals)
__device__ __half g_xh[M_TOTAL * DIMS];                 // X fp16
__device__ __half g_wth[2 * KSZ * DIMS];                // [n=256][k=1024] W^T fp16
__device__ __half g_keys_h[M_TOTAL * KSZ];              // keys fp16 [tok][dim]
__device__ __half g_valsT_h[(size_t)BATCH * KSZ * SEQ]; // vals^T fp16 [b][dim][tok]

// ---------------------------------------------------------------------------
// helpers
// ---------------------------------------------------------------------------
__device__ __forceinline__ void cp16a(unsigned daddr, const void* src) {
    asm volatile("cp.async.cg.shared.global [%0], [%1], 16;" :: "r"(daddr), "l"(src));
}
#define CP_COMMIT() asm volatile("cp.async.commit_group;")
#define CP_WAIT(n)  asm volatile("cp.async.wait_group %0;" :: "n"(n))

__device__ __forceinline__ void mma_f16(float* c,
        unsigned a0, unsigned a1, unsigned a2, unsigned a3,
        unsigned b0, unsigned b1) {
    asm volatile(
        "mma.sync.aligned.m16n8k16.row.col.f32.f16.f16.f32 "
        "{%0,%1,%2,%3}, {%4,%5,%6,%7}, {%8,%9}, {%0,%1,%2,%3};"
        : "+f"(c[0]), "+f"(c[1]), "+f"(c[2]), "+f"(c[3])
        : "r"(a0), "r"(a1), "r"(a2), "r"(a3), "r"(b0), "r"(b1));
}

__device__ __forceinline__ void ldmat_x4(unsigned& r0, unsigned& r1,
                                         unsigned& r2, unsigned& r3, unsigned saddr) {
    asm volatile("ldmatrix.sync.aligned.m8n8.x4.shared.b16 {%0,%1,%2,%3}, [%4];"
        : "=r"(r0), "=r"(r1), "=r"(r2), "=r"(r3) : "r"(saddr));
}

__device__ __forceinline__ unsigned packh2(float lo, float hi) {
    __half2 h = __floats2half2_rn(lo, hi);
    return *(unsigned*)&h;
}

#define LDM_A_ROW(lane) ((((lane) >> 3) & 1) * 8 + ((lane) & 7))
#define LDM_A_K(lane)   ((((lane) >> 4) & 1) * 8)
#define LDM_B_ROW(lane) ((((lane) >> 4) & 1) * 8 + ((lane) & 7))
#define LDM_B_K(lane)   ((((lane) >> 3) & 1) * 8)

// ---------------------------------------------------------------------------
// Kernel P: fused prep. Blocks [0,4096): 4 X rows -> out copy + g_xh fp16
// (4 independent LDGs hoisted for MLP). Blocks [4096,4096+64): W transpose.
// ---------------------------------------------------------------------------
#define XBLKS 4096
__global__ __launch_bounds__(256) void prep_kernel(
        const float* __restrict__ X, float* __restrict__ out,
        const float* __restrict__ Wk, const float* __restrict__ Wv) {
    __shared__ float wt[128][33];
    const int tid = threadIdx.x;
    if (blockIdx.x < XBLKS) {
        const size_t r0 = (size_t)blockIdx.x * 4 + (tid >> 7);   // row and row+2
        const int e0 = (tid & 127) * 8;
        const float* s0 = X + r0 * DIMS + e0;
        const float* s1 = X + (r0 + 2) * DIMS + e0;
        float4 a0 = *(const float4*)(s0);
        float4 a1 = *(const float4*)(s0 + 4);
        float4 b0 = *(const float4*)(s1);
        float4 b1 = *(const float4*)(s1 + 4);
        *(float4*)(out + r0 * OUTD + e0)           = a0;
        *(float4*)(out + r0 * OUTD + e0 + 4)       = a1;
        *(float4*)(out + (r0 + 2) * OUTD + e0)     = b0;
        *(float4*)(out + (r0 + 2) * OUTD + e0 + 4) = b1;
        uint4 ha, hb;
        ha.x = packh2(a0.x, a0.y); ha.y = packh2(a0.z, a0.w);
        ha.z = packh2(a1.x, a1.y); ha.w = packh2(a1.z, a1.w);
        hb.x = packh2(b0.x, b0.y); hb.y = packh2(b0.z, b0.w);
        hb.z = packh2(b1.x, b1.y); hb.w = packh2(b1.z, b1.w);
        *(uint4*)(g_xh + r0 * DIMS + e0)       = ha;
        *(uint4*)(g_xh + (r0 + 2) * DIMS + e0) = hb;
    } else {
        const int wb = blockIdx.x - XBLKS;   // 0..63
        const int mat = wb >> 5, tw = wb & 31;
        const int k0 = (tw >> 2) * 128, n0 = (tw & 3) * 32;
        const float* W = mat ? Wv : Wk;
        #pragma unroll
        for (int i = 0; i < 16; i++) {
            int idx = tid + i * 256;
            int kk = idx >> 5, nn = idx & 31;
            wt[kk][nn] = W[(size_t)(k0 + kk) * KSZ + n0 + nn];
        }
        __syncthreads();
        #pragma unroll
        for (int i = 0; i < 16; i++) {
            int idx = tid + i * 256;
            int nn = idx >> 7, kk = idx & 127;
            g_wth[(size_t)(mat * KSZ + n0 + nn) * DIMS + k0 + kk] =
                __float2half_rn(wt[kk][nn]);
        }
    }
}

// ---------------------------------------------------------------------------
// Kernel G: fused KV projection GEMM (lean).
// BM=128, BN=256, BK=64, 512 threads (16 warps 4m x 4n, warp tile 32x64).
// ---------------------------------------------------------------------------
#define GBK 64
#define ALD 72
#define BLD 72
#define GA_H (128 * ALD)
#define GB_H (256 * BLD)
#define GB_OFF (GA_H * 2)
#define GBUF_BYTES ((GA_H + GB_H) * 2)            // 55296
#define GEMM_SMEM_BYTES (2 * GBUF_BYTES)          // 110592

__global__ __launch_bounds__(512, 1) void kv_gemm_f16(
        const float* __restrict__ bk, const float* __restrict__ bv) {
    extern __shared__ char smc[];
    const unsigned sbase = (unsigned)__cvta_generic_to_shared(smc);
    const int tid = threadIdx.x, lane = tid & 31, wid = tid >> 5;
    const int g = lane >> 2, t = lane & 3;
    const int wm = wid & 3, wn = wid >> 2;
    const int m0 = blockIdx.x * 128;

    const int raA = LDM_A_ROW(lane), kaA = LDM_A_K(lane);
    const int rbB = LDM_B_ROW(lane), kbB = LDM_B_K(lane);

    #define G_LOAD(bb, k0) do {                                               \
        unsigned ab = sbase + (bb) * GBUF_BYTES;                              \
        _Pragma("unroll")                                                     \
        for (int i = 0; i < 2; i++) {                                         \
            int idx = tid + i * 512;                                          \
            int row = idx >> 3, ch = idx & 7;                                 \
            cp16a(ab + (row * ALD + ch * 8) * 2,                              \
                  g_xh + (size_t)(m0 + row) * DIMS + (k0) + ch * 8);          \
        }                                                                     \
        _Pragma("unroll")                                                     \
        for (int i = 0; i < 4; i++) {                                         \
            int idx = tid + i * 512;                                          \
            int row = idx >> 3, ch = idx & 7;                                 \
            cp16a(ab + GB_OFF + (row * BLD + ch * 8) * 2,                     \
                  g_wth + (size_t)row * DIMS + (k0) + ch * 8);                \
        }                                                                     \
    } while (0)

    float acc[2][8][4];
    #pragma unroll
    for (int mt = 0; mt < 2; mt++)
        #pragma unroll
        for (int nt = 0; nt < 8; nt++)
            #pragma unroll
            for (int i = 0; i < 4; i++) acc[mt][nt][i] = 0.f;

    G_LOAD(0, 0);
    CP_COMMIT();

    const int NK = DIMS / GBK;   // 16
    for (int kk0 = 0; kk0 < NK; kk0++) {
        if (kk0 + 1 < NK) {
            G_LOAD((kk0 + 1) & 1, (kk0 + 1) * GBK);
            CP_COMMIT();
            CP_WAIT(1);
        } else {
            CP_WAIT(0);
        }
        __syncthreads();

        const unsigned ab = sbase + (kk0 & 1) * GBUF_BYTES;
        const unsigned aW = ab + ((wm * 32 + raA) * ALD + kaA) * 2;
        const unsigned bW = ab + GB_OFF + ((wn * 64 + rbB) * BLD + kbB) * 2;
        #pragma unroll
        for (int ks = 0; ks < 4; ks++) {
            const int kk = ks * 16;
            unsigned a[2][4];
            #pragma unroll
            for (int mt = 0; mt < 2; mt++)
                ldmat_x4(a[mt][0], a[mt][1], a[mt][2], a[mt][3],
                         aW + (mt * 16 * ALD + kk) * 2);
            #pragma unroll
            for (int ntp = 0; ntp < 4; ntp++) {
                unsigned b0a, b1a, b0b, b1b;
                ldmat_x4(b0a, b1a, b0b, b1b, bW + (ntp * 16 * BLD + kk) * 2);
                #pragma unroll
                for (int mt = 0; mt < 2; mt++) {
                    mma_f16(acc[mt][2 * ntp],
                            a[mt][0], a[mt][1], a[mt][2], a[mt][3], b0a, b1a);
                    mma_f16(acc[mt][2 * ntp + 1],
                            a[mt][0], a[mt][1], a[mt][2], a[mt][3], b0b, b1b);
                }
            }
        }
        __syncthreads();
    }

    if (wn < 2) {
        #pragma unroll
        for (int mt = 0; mt < 2; mt++) {
            int row = m0 + wm * 32 + mt * 16 + g;
            #pragma unroll
            for (int nt = 0; nt < 8; nt++) {
                int col = wn * 64 + nt * 8 + 2 * t;
                float b0 = bk[col], b1 = bk[col + 1];
                *(unsigned*)&g_keys_h[(size_t)row * KSZ + col] =
                    packh2(acc[mt][nt][0] + b0, acc[mt][nt][1] + b1);
                *(unsigned*)&g_keys_h[(size_t)(row + 8) * KSZ + col] =
                    packh2(acc[mt][nt][2] + b0, acc[mt][nt][3] + b1);
            }
        }
        __syncthreads();
    } else {
        __half* Vst = (__half*)smc;   // [dim 128][tok 128+8]
        #pragma unroll
        for (int mt = 0; mt < 2; mt++) {
            int r = wm * 32 + mt * 16 + g;
            #pragma unroll
            for (int nt = 0; nt < 8; nt++) {
                int dcol = (wn - 2) * 64 + nt * 8 + 2 * t;
                float b0 = bv[dcol], b1 = bv[dcol + 1];
                Vst[(dcol    ) * 136 + r    ] = __float2half_rn(acc[mt][nt][0] + b0);
                Vst[(dcol + 1) * 136 + r    ] = __float2half_rn(acc[mt][nt][1] + b1);
                Vst[(dcol    ) * 136 + r + 8] = __float2half_rn(acc[mt][nt][2] + b0);
                Vst[(dcol + 1) * 136 + r + 8] = __float2half_rn(acc[mt][nt][3] + b1);
            }
        }
        __syncthreads();
    }
    {
        __half* Vst = (__half*)smc;
        const int bb = m0 >> 11;
        const int tloc = m0 & 2047;
        #pragma unroll
        for (int i = 0; i < 4; i++) {
            int idx = tid + i * 512;
            int col = idx >> 4, ch = idx & 15;
            uint4 v = *(uint4*)&Vst[col * 136 + ch * 8];
            *(uint4*)&g_valsT_h[((size_t)bb * KSZ + col) * SEQ + tloc + ch * 8] = v;
        }
    }
}

// ---------------------------------------------------------------------------
// Kernel A: causal flash attention, (p,31-p) pairing, register-repacked P,
// SINGLE group barrier per iteration (next-tile loads issued after the top
// barrier: reads of that buffer finished in iteration j-1, which precedes
// every warp's top barrier of iteration j in program order).
// ---------------------------------------------------------------------------
#define AQ 64
#define AK 64
#define KLD 136
#define VLD 72
#define NQT (SEQ / AQ)               // 32
#define K_TILE_H (AK * KLD)
#define VT_TILE_H (KSZ * VLD)
#define GOFF_K0 0
#define GOFF_K1 (K_TILE_H)
#define GOFF_VT0 (2 * K_TILE_H)
#define GOFF_VT1 (2 * K_TILE_H + VT_TILE_H)
#define GRP_H (2 * K_TILE_H + 2 * VT_TILE_H)
#define ATTN_SMEM_BYTES (2 * GRP_H * 2)             // 143360

__global__ __launch_bounds__(256, 1) void attn_kernel(float* __restrict__ out) {
    extern __shared__ char smc[];
    const int tid = threadIdx.x, lane = tid & 31, wid = tid >> 5;
    const int g = lane >> 2, t = lane & 3;
    const int grp = wid >> 2, wg = wid & 3, gt = tid & 127;
    const int barid = grp + 1;
    #define GBAR() asm volatile("bar.sync %0, 128;" :: "r"(barid))

    char* gbase = smc + grp * GRP_H * 2;
    const unsigned sgb = (unsigned)__cvta_generic_to_shared(gbase);

    const int pairIdx = blockIdx.x;
    const int bq = blockIdx.y;
    const int qt = grp ? (NQT - 1 - pairIdx) : pairIdx;   // balanced pairing
    const int qbase = qt * AQ;
    const int nkt = qt + 1;
    const __half* keys = g_keys_h + (size_t)bq * SEQ * KSZ;
    const __half* valsT = g_valsT_h + (size_t)bq * KSZ * SEQ;
    const float scale = 0.08838834764831843f;   // 1/sqrt(128)

    const int raA = LDM_A_ROW(lane), kaA = LDM_A_K(lane);
    const int rbB = LDM_B_ROW(lane), kbB = LDM_B_K(lane);
    const int rw = wg * 16;

    #define LOAD_KV(buf, kbase) do {                                          \
        _Pragma("unroll")                                                     \
        for (int i = 0; i < 8; i++) {                                         \
            int idx = gt + i * 128;                                           \
            int row = idx >> 4, ch = idx & 15;                                \
            cp16a(sgb + ((buf ? GOFF_K1 : GOFF_K0) + row * KLD + ch * 8) * 2, \
                  keys + (size_t)((kbase) + row) * KSZ + ch * 8);             \
        }                                                                     \
        _Pragma("unroll")                                                     \
        for (int i = 0; i < 8; i++) {                                         \
            int idx = gt + i * 128;                                           \
            int row = idx >> 3, ch = idx & 7;                                 \
            cp16a(sgb + ((buf ? GOFF_VT1 : GOFF_VT0) + row * VLD + ch * 8) * 2, \
                  valsT + (size_t)row * SEQ + (kbase) + ch * 8);              \
        }                                                                     \
    } while (0)

    // stage Q through K0 region
    #pragma unroll
    for (int i = 0; i < 8; i++) {
        int idx = gt + i * 128;
        int row = idx >> 4, ch = idx & 15;
        cp16a(sgb + (row * KLD + ch * 8) * 2,
              keys + (size_t)(qbase + row) * KSZ + ch * 8);
    }
    CP_COMMIT();
    CP_WAIT(0);
    GBAR();

    // Q fragments via ldmatrix (a-type)
    unsigned qa[8][4];
    {
        const unsigned qW = sgb + ((rw + raA) * KLD + kaA) * 2;
        #pragma unroll
        for (int ks = 0; ks < 8; ks++)
            ldmat_x4(qa[ks][0], qa[ks][1], qa[ks][2], qa[ks][3], qW + ks * 32);
    }
    GBAR();

    LOAD_KV(0, 0);
    CP_COMMIT();

    float O[16][4];
    #pragma unroll
    for (int nt = 0; nt < 16; nt++)
        #pragma unroll
        for (int i = 0; i < 4; i++) O[nt][i] = 0.f;
    float mrow[2] = {-1e30f, -1e30f};
    float lrow[2] = {0.f, 0.f};

    for (int j = 0; j < nkt; j++) {
        CP_WAIT(0);
        GBAR();
        if (j + 1 < nkt) {
            LOAD_KV((j + 1) & 1, (j + 1) * AK);
            CP_COMMIT();
        }

        const unsigned kW = sgb + ((j & 1) ? GOFF_K1 : GOFF_K0) * 2
                          + (rbB * KLD + kbB) * 2;
        const unsigned vW = sgb + ((j & 1) ? GOFF_VT1 : GOFF_VT0) * 2
                          + (rbB * VLD + kbB) * 2;
        const int kbase = j * AK;

        // S = Q @ K^T : 16 rows x 64 keys
        float s[8][4];
        #pragma unroll
        for (int nt = 0; nt < 8; nt++)
            #pragma unroll
            for (int i = 0; i < 4; i++) s[nt][i] = 0.f;

        #pragma unroll
        for (int ks = 0; ks < 8; ks++) {
            #pragma unroll
            for (int ntp = 0; ntp < 4; ntp++) {
                unsigned b0a, b1a, b0b, b1b;
                ldmat_x4(b0a, b1a, b0b, b1b, kW + (ntp * 16 * KLD + ks * 16) * 2);
                mma_f16(s[2 * ntp],
                        qa[ks][0], qa[ks][1], qa[ks][2], qa[ks][3], b0a, b1a);
                mma_f16(s[2 * ntp + 1],
                        qa[ks][0], qa[ks][1], qa[ks][2], qa[ks][3], b0b, b1b);
            }
        }

        #pragma unroll
        for (int nt = 0; nt < 8; nt++)
            #pragma unroll
            for (int i = 0; i < 4; i++) s[nt][i] *= scale;

        // causal mask on diagonal tile only, exactly -100
        if (j == nkt - 1) {
            const int qg0 = qbase + rw + g;
            const int qg1 = qg0 + 8;
            #pragma unroll
            for (int nt = 0; nt < 8; nt++) {
                int kg = kbase + nt * 8 + 2 * t;
                if (kg     > qg0) s[nt][0] = -100.0f;
                if (kg + 1 > qg0) s[nt][1] = -100.0f;
                if (kg     > qg1) s[nt][2] = -100.0f;
                if (kg + 1 > qg1) s[nt][3] = -100.0f;
            }
        }

        // online softmax; O-rescale only when the running max changes
        #pragma unroll
        for (int h = 0; h < 2; h++) {
            float mx = -1e30f;
            #pragma unroll
            for (int nt = 0; nt < 8; nt++)
                mx = fmaxf(mx, fmaxf(s[nt][2 * h], s[nt][2 * h + 1]));
            mx = fmaxf(mx, __shfl_xor_sync(0xffffffffu, mx, 1));
            mx = fmaxf(mx, __shfl_xor_sync(0xffffffffu, mx, 2));
            if (mx > mrow[h]) {
                float alpha = __expf(mrow[h] - mx);
                mrow[h] = mx;
                lrow[h] *= alpha;
                #pragma unroll
                for (int nt = 0; nt < 16; nt++) {
                    O[nt][2 * h]     *= alpha;
                    O[nt][2 * h + 1] *= alpha;
                }
            }
            float m = mrow[h];
            float sum = 0.f;
            #pragma unroll
            for (int nt = 0; nt < 8; nt++) {
                float p0 = __expf(s[nt][2 * h] - m);
                float p1 = __expf(s[nt][2 * h + 1] - m);
                s[nt][2 * h] = p0; s[nt][2 * h + 1] = p1;
                sum += p0 + p1;
            }
            sum += __shfl_xor_sync(0xffffffffu, sum, 1);
            sum += __shfl_xor_sync(0xffffffffu, sum, 2);
            lrow[h] += sum;
        }

        // O += P @ V : P A-fragments repacked in registers from S accumulators
        #pragma unroll
        for (int ks = 0; ks < 4; ks++) {
            unsigned pa0 = packh2(s[2 * ks][0], s[2 * ks][1]);
            unsigned pa1 = packh2(s[2 * ks][2], s[2 * ks][3]);
            unsigned pa2 = packh2(s[2 * ks + 1][0], s[2 * ks + 1][1]);
            unsigned pa3 = packh2(s[2 * ks + 1][2], s[2 * ks + 1][3]);
            #pragma unroll
            for (int ntp = 0; ntp < 8; ntp++) {
                unsigned b0a, b1a, b0b, b1b;
                ldmat_x4(b0a, b1a, b0b, b1b, vW + (ntp * 16 * VLD + ks * 16) * 2);
                mma_f16(O[2 * ntp], pa0, pa1, pa2, pa3, b0a, b1a);
                mma_f16(O[2 * ntp + 1], pa0, pa1, pa2, pa3, b0b, b1b);
            }
        }
    }

    // epilogue: normalize, write out[:, 1024:1152]
    {
        float inv0 = 1.0f / lrow[0];
        float inv1 = 1.0f / lrow[1];
        int qg0 = qbase + rw + g;
        size_t base0 = ((size_t)bq * SEQ + qg0) * OUTD + DIMS;
        size_t base1 = base0 + (size_t)8 * OUTD;
        #pragma unroll
        for (int nt = 0; nt < 16; nt++) {
            int c = nt * 8 + 2 * t;
            *(float2*)(out + base0 + c) = make_float2(O[nt][0] * inv0, O[nt][1] * inv0);
            *(float2*)(out + base1 + c) = make_float2(O[nt][2] * inv1, O[nt][3] * inv1);
        }
    }
}

// ---------------------------------------------------------------------------
extern "C" void kernel_launch(void* const* d_in, const int* in_sizes, int n_in,
                              void* d_out, int out_size) {
    const float* X  = (const float*)d_in[0];
    const float* Wk = (const float*)d_in[1];
    const float* bk = (const float*)d_in[2];
    const float* Wv = (const float*)d_in[3];
    const float* bv = (const float*)d_in[4];
    float* out = (float*)d_out;

    prep_kernel<<<XBLKS + 64, 256>>>(X, out, Wk, Wv);

    cudaFuncSetAttribute(kv_gemm_f16, cudaFuncAttributeMaxDynamicSharedMemorySize,
                         GEMM_SMEM_BYTES);
    kv_gemm_f16<<<M_TOTAL / 128, 512, GEMM_SMEM_BYTES>>>(bk, bv);

    cudaFuncSetAttribute(attn_kernel, cudaFuncAttributeMaxDynamicSharedMemorySize,
                         ATTN_SMEM_BYTES);
    attn_kernel<<<dim3(NQT / 2, BATCH), 256, ATTN_SMEM_BYTES>>>(out);
}